// round 11
// baseline (speedup 1.0000x reference)
#include <cuda_runtime.h>
#include <math.h>

#define GS   28
#define NB   128
#define NH   64
#define ND   4
#define G5   320
#define KK2  128
#define FCH  512
#define NOUT 10
#define NBLK      448     // 28 slots * 4 dirs * 4 chunk16
#define BLK_PER_DIR 112u

// dynamic smem (floats): Us[128][80] persistent + xs[128]
#define US_SZ    10240
#define XS_OFF   10240
#define SMEM_FLOATS (XS_OFF + 128)
#define SMEM_BYTES  (SMEM_FLOATS * 4)   // 41472

// Recurrent state, TRANSPOSED: [dir][row][col][h][batch]
__device__ float g_h[ND][GS][GS][NH][NB];
__device__ float g_c[ND][GS][GS][NH][NB];
__device__ float g_z1[NB][FCH];

struct __align__(128) Bar { unsigned gen; unsigned cnt; };
__device__ Bar g_bar[ND];

typedef unsigned long long u64;

__device__ __forceinline__ void fma2(u64 &d, u64 a, u64 b) {
    asm("fma.rn.f32x2 %0, %1, %2, %0;" : "+l"(d) : "l"(a), "l"(b));
}
__device__ __forceinline__ u64 dup2(float v) {
    u64 r; asm("mov.b64 %0, {%1, %1};" : "=l"(r) : "f"(v)); return r;
}
__device__ __forceinline__ u64 pack2(float lo, float hi) {
    u64 r; asm("mov.b64 %0, {%1, %2};" : "=l"(r) : "f"(lo), "f"(hi)); return r;
}
__device__ __forceinline__ void unpack2(u64 v, float &lo, float &hi) {
    asm("mov.b64 {%0, %1}, %2;" : "=f"(lo), "=f"(hi) : "l"(v));
}
__device__ __forceinline__ float sigf(float x) { return 1.0f / (1.0f + __expf(-x)); }
__device__ __forceinline__ float tanh_acc(float x) {
    float e = __expf(-2.0f * fabsf(x));
    float t = (1.0f - e) / (1.0f + e);
    return copysignf(t, x);
}

__global__ void init_kernel() {
    if (threadIdx.x < ND) { g_bar[threadIdx.x].gen = 0u; g_bar[threadIdx.x].cnt = 0u; }
}

// Per-dir sense-reversing barrier (112 blocks per dir), nanosleep backoff.
// (Proven construct from R4/R9 -- unchanged.)
__device__ __forceinline__ void dir_barrier(int dir, int tid, unsigned gen) {
    __threadfence();
    __syncthreads();
    if (tid == 0) {
        if (atomicAdd(&g_bar[dir].cnt, 1u) == BLK_PER_DIR - 1u) {
            g_bar[dir].cnt = 0u;
            asm volatile("st.release.gpu.global.b32 [%0], %1;"
                         :: "l"(&g_bar[dir].gen), "r"(gen + 1u) : "memory");
        } else {
            unsigned v;
            do {
                __nanosleep(64);
                asm volatile("ld.acquire.gpu.global.b32 %0, [%1];"
                             : "=r"(v) : "l"(&g_bar[dir].gen) : "memory");
            } while (v == gen);
        }
    }
    __syncthreads();
    __threadfence();
}

// Persistent wavefront: transposed state, direct-LDG A operand, persistent Us.
// blk decode identical to R4/R9: chunk = blk&3, dir = (blk>>2)&3, slot = blk>>4.
// 128 threads: tx = tid&15 (h in chunk16), ty = tid>>4 (8 groups of 16 batch).
__global__ __launch_bounds__(128, 4) void mdlstm_wave(
    const float* __restrict__ x,
    const float* __restrict__ Wx,
    const float* __restrict__ U,
    const float* __restrict__ bias)
{
    extern __shared__ __align__(16) float smf[];

    int blk   = blockIdx.x;
    int chunk = blk & 3;
    int dir   = (blk >> 2) & 3;
    int slot  = blk >> 4;

    int tid = threadIdx.x;
    int tx  = tid & 15;
    int ty  = tid >> 4;           // 0..7
    int h0  = chunk * 16;

    const float* Ud  = U    + dir * (KK2 * G5);
    const float* Wxd = Wx   + dir * G5;
    const float* bd  = bias + dir * G5;

    // ---- one-time: persistent U slice into smem ----
    // Us[kglob][col], col = gate*16 + hh (same values/order as R9)
    for (int i = tid; i < US_SZ; i += 128) {
        int kk   = i / 80;
        int col  = i - kk * 80;
        int gate = col >> 4;
        int hh   = col & 15;
        smf[i] = Ud[kk * G5 + gate * 64 + h0 + hh];
    }

    int hcol = h0 + tx;
    float wxb[5], bb[5];
    #pragma unroll
    for (int g = 0; g < 5; ++g) {
        wxb[g] = Wxd[g * 64 + hcol];
        bb[g]  = bd [g * 64 + hcol];
    }
    __syncthreads();

    unsigned gen = 0u;

    for (int d = 0; d < 2 * GS - 1; ++d) {
        int rlo = d - (GS - 1); if (rlo < 0) rlo = 0;
        int k = d + 1;
        if (2 * GS - 1 - d < k) k = 2 * GS - 1 - d;
        if (k > GS) k = GS;

        if (slot < k) {
            int r = rlo + slot;
            int c = d - r;

            // transposed neighbor state: [h][b]
            const float* hLt = (c > 0) ? &g_h[dir][r][c-1][0][0] : nullptr;
            const float* hUt = (r > 0) ? &g_h[dir][r-1][c][0][0] : nullptr;

            int rr = (dir & 2) ? (GS - 1 - r) : r;
            int cc = (dir & 1) ? (GS - 1 - c) : c;
            smf[XS_OFF + tid] = x[tid * (GS * GS) + rr * GS + cc];
            __syncthreads();

            u64 acc[8][5];
            #pragma unroll
            for (int p = 0; p < 8; ++p)
                #pragma unroll
                for (int g = 0; g < 5; ++g) acc[p][g] = 0ull;

            // K half: 64 rows of U starting at Ubase; A = srcT[kk][b] pairs
            // (skipping a null half == fma with exact zeros)
            #define K_HALF(srcT, Ubase)                                         \
            {                                                                    \
                const u64* abase = (const u64*)((srcT) + (ty << 4));             \
                const float* Ub = (Ubase);                                       \
                _Pragma("unroll 2")                                              \
                for (int kk = 0; kk < 64; ++kk) {                                \
                    u64 a[8], bf[5];                                             \
                    const u64* ap = abase + kk * (NB / 2);                       \
                    _Pragma("unroll")                                            \
                    for (int p = 0; p < 8; ++p) a[p] = ap[p];                    \
                    _Pragma("unroll")                                            \
                    for (int g = 0; g < 5; ++g)                                  \
                        bf[g] = dup2(Ub[kk * 80 + g * 16 + tx]);                 \
                    _Pragma("unroll")                                            \
                    for (int p = 0; p < 8; ++p)                                  \
                        _Pragma("unroll")                                        \
                        for (int g = 0; g < 5; ++g)                              \
                            fma2(acc[p][g], a[p], bf[g]);                        \
                }                                                                \
            }

            if (hLt) K_HALF(hLt, &smf[0])
            if (hUt) K_HALF(hUt, &smf[64 * 80])
            #undef K_HALF

            // Fused gate epilogue (same math/order as R9; transposed c/h I/O)
            const float* cLt = (c > 0) ? &g_c[dir][r][c-1][0][0] : nullptr;
            const float* cUt = (r > 0) ? &g_c[dir][r-1][c][0][0] : nullptr;
            u64* hOut = (u64*)&g_h[dir][r][c][0][0];
            u64* cOut = (u64*)&g_c[dir][r][c][0][0];

            #pragma unroll
            for (int p = 0; p < 8; ++p) {
                int row0 = ty * 16 + 2 * p;
                int pofs = (hcol * NB + row0) >> 1;   // u64 index
                float zl[5], zh[5];
                #pragma unroll
                for (int g = 0; g < 5; ++g) unpack2(acc[p][g], zl[g], zh[g]);
                float cl0 = 0.f, cl1 = 0.f, cu0 = 0.f, cu1 = 0.f;
                if (cLt) unpack2(((const u64*)cLt)[pofs], cl0, cl1);
                if (cUt) unpack2(((const u64*)cUt)[pofs], cu0, cu1);
                float cn2[2], hn2[2];
                #pragma unroll
                for (int half = 0; half < 2; ++half) {
                    int row = row0 + half;
                    float xv = smf[XS_OFF + row];
                    float z0 = (half ? zh[0] : zl[0]) + xv * wxb[0] + bb[0]; // i
                    float z1 = (half ? zh[1] : zl[1]) + xv * wxb[1] + bb[1]; // f_left
                    float z2 = (half ? zh[2] : zl[2]) + xv * wxb[2] + bb[2]; // f_up
                    float z3 = (half ? zh[3] : zl[3]) + xv * wxb[3] + bb[3]; // o
                    float z4 = (half ? zh[4] : zl[4]) + xv * wxb[4] + bb[4]; // g
                    float cl = half ? cl1 : cl0;
                    float cu = half ? cu1 : cu0;
                    float cn = sigf(z0) * tanh_acc(z4) + sigf(z1) * cl + sigf(z2) * cu;
                    float hn = sigf(z3) * tanh_acc(cn);
                    cn2[half] = cn;
                    hn2[half] = hn;
                }
                cOut[pofs] = pack2(cn2[0], cn2[1]);
                hOut[pofs] = pack2(hn2[0], hn2[1]);
            }
        }

        dir_barrier(dir, tid, gen);
        gen++;
    }
}

// z1 = relu(hfinal @ W1 + b1); hfinal[b][dir*64+h] = g_h[dir][27][27][h][b]
__global__ void head1_kernel(const float* __restrict__ W1,
                             const float* __restrict__ b1)
{
    __shared__ float a[ND * NH];
    int b = blockIdx.y;
    int n = blockIdx.x * 256 + threadIdx.x;
    {
        int dcol = threadIdx.x;
        int dir = dcol >> 6, hh = dcol & 63;
        a[dcol] = g_h[dir][GS - 1][GS - 1][hh][b];
    }
    __syncthreads();
    float acc = b1[n];
    #pragma unroll 8
    for (int k = 0; k < ND * NH; ++k)
        acc = fmaf(a[k], W1[k * FCH + n], acc);
    g_z1[b][n] = fmaxf(acc, 0.0f);
}

// out = softmax(z1 @ W2 + b2)
__global__ void head2_kernel(const float* __restrict__ W2,
                             const float* __restrict__ b2,
                             float* __restrict__ out)
{
    __shared__ float logit[NOUT];
    int b    = blockIdx.x;
    int tid  = threadIdx.x;        // 320 threads = 10 warps
    int w    = tid >> 5;
    int lane = tid & 31;
    float acc = 0.0f;
    for (int k = lane; k < FCH; k += 32)
        acc = fmaf(g_z1[b][k], W2[k * NOUT + w], acc);
    #pragma unroll
    for (int o = 16; o; o >>= 1)
        acc += __shfl_down_sync(0xffffffffu, acc, o);
    if (lane == 0) logit[w] = acc + b2[w];
    __syncthreads();
    if (tid == 0) {
        float m = -1e30f;
        #pragma unroll
        for (int j = 0; j < NOUT; ++j) m = fmaxf(m, logit[j]);
        float e[NOUT], s = 0.0f;
        #pragma unroll
        for (int j = 0; j < NOUT; ++j) { e[j] = __expf(logit[j] - m); s += e[j]; }
        float inv = 1.0f / s;
        #pragma unroll
        for (int j = 0; j < NOUT; ++j) out[b * NOUT + j] = e[j] * inv;
    }
}

extern "C" void kernel_launch(void* const* d_in, const int* in_sizes, int n_in,
                              void* d_out, int out_size)
{
    const float* x  = (const float*)d_in[0];
    const float* Wx = (const float*)d_in[1];
    const float* U  = (const float*)d_in[2];
    const float* bb = (const float*)d_in[3];
    const float* W1 = (const float*)d_in[4];
    const float* b1 = (const float*)d_in[5];
    const float* W2 = (const float*)d_in[6];
    const float* b2 = (const float*)d_in[7];
    float* out = (float*)d_out;

    cudaFuncSetAttribute(mdlstm_wave,
                         cudaFuncAttributeMaxDynamicSharedMemorySize, SMEM_BYTES);

    init_kernel<<<1, 32>>>();
    mdlstm_wave<<<NBLK, 128, SMEM_BYTES>>>(x, Wx, U, bb);
    head1_kernel<<<dim3(2, NB), 256>>>(W1, b1);
    head2_kernel<<<NB, 320>>>(W2, b2, out);
}

// round 12
// speedup vs baseline: 1.2514x; 1.2514x over previous
#include <cuda_runtime.h>
#include <math.h>

#define GS   28
#define NB   128
#define NH   64
#define ND   4
#define G5   320
#define KK2  128
#define FCH  512
#define NOUT 10
#define NBLK      448     // 28 slots * 4 dirs * 4 chunk16
#define BLK_PER_DIR 112u

// dynamic smem (floats):
//   Us[128][80]           : 10240  (persistent U slice, (dir,chunk)-specific)
//   Aw[4 warps][2][8][36] :  2304  (warp-private A k-tiles, transposed, padded)
//   xs[128]               :   128
#define US_SZ    10240
#define AW_OFF   10240
#define AW_WARP  576           // 2*8*36
#define XS_OFF   (AW_OFF + 4 * AW_WARP)   // 12544
#define SMEM_FLOATS (XS_OFF + 128)
#define SMEM_BYTES  (SMEM_FLOATS * 4)     // 50688

// Recurrent state: [dir][row][col][batch][h]   (R9-proven layout)
__device__ float g_h[ND][GS][GS][NB][NH];
__device__ float g_c[ND][GS][GS][NB][NH];
__device__ float g_z1[NB][FCH];

struct __align__(128) Bar { unsigned gen; unsigned cnt; };
__device__ Bar g_bar[ND];

typedef unsigned long long u64;

__device__ __forceinline__ void fma2(u64 &d, u64 a, u64 b) {
    asm("fma.rn.f32x2 %0, %1, %2, %0;" : "+l"(d) : "l"(a), "l"(b));
}
__device__ __forceinline__ u64 dup2(float v) {
    u64 r; asm("mov.b64 %0, {%1, %1};" : "=l"(r) : "f"(v)); return r;
}
__device__ __forceinline__ void unpack2(u64 v, float &lo, float &hi) {
    asm("mov.b64 {%0, %1}, %2;" : "=f"(lo), "=f"(hi) : "l"(v));
}
__device__ __forceinline__ float sigf(float x) { return 1.0f / (1.0f + __expf(-x)); }
__device__ __forceinline__ float tanh_acc(float x) {
    float e = __expf(-2.0f * fabsf(x));
    float t = (1.0f - e) / (1.0f + e);
    return copysignf(t, x);
}

__global__ void init_kernel() {
    if (threadIdx.x < ND) { g_bar[threadIdx.x].gen = 0u; g_bar[threadIdx.x].cnt = 0u; }
}

// Per-dir sense-reversing barrier (112 blocks per dir), nanosleep backoff.
// (Proven construct from R4/R9 -- unchanged.)
__device__ __forceinline__ void dir_barrier(int dir, int tid, unsigned gen) {
    __threadfence();
    __syncthreads();
    if (tid == 0) {
        if (atomicAdd(&g_bar[dir].cnt, 1u) == BLK_PER_DIR - 1u) {
            g_bar[dir].cnt = 0u;
            asm volatile("st.release.gpu.global.b32 [%0], %1;"
                         :: "l"(&g_bar[dir].gen), "r"(gen + 1u) : "memory");
        } else {
            unsigned v;
            do {
                __nanosleep(64);
                asm volatile("ld.acquire.gpu.global.b32 %0, [%1];"
                             : "=r"(v) : "l"(&g_bar[dir].gen) : "memory");
            } while (v == gen);
        }
    }
    __syncthreads();
    __threadfence();
}

// One K half (64 k-values): warp-private A staging, double-buffered, syncwarp only.
// K order identical to R9: tiles t = 0..7, kk = 0..7 inside; fma order p then g.
__device__ __forceinline__ void k_half(
    const float* __restrict__ src,   // neighbor h state, [b][h]
    const float* __restrict__ Uh,    // &smf[uofs*80]
    float* __restrict__ Aw,          // this warp's A region (2 buffers)
    int lane, int hw, int tx,
    u64 (&acc)[8][5])
{
    const float* srow = src + (32 * (int)(lane >= 0 ? 0 : 0) /*dummy*/ + 0);
    // (real srow computed by caller offset; see call site) -- placeholder removed below
    (void)srow;
}

// Persistent wavefront: R9 structure, warp-private A tiles, LDS.128 A consume.
// blk decode identical to R4/R9: chunk = blk&3, dir = (blk>>2)&3, slot = blk>>4.
__global__ __launch_bounds__(128, 4) void mdlstm_wave(
    const float* __restrict__ x,
    const float* __restrict__ Wx,
    const float* __restrict__ U,
    const float* __restrict__ bias)
{
    extern __shared__ __align__(16) float smf[];

    int blk   = blockIdx.x;
    int chunk = blk & 3;
    int dir   = (blk >> 2) & 3;
    int slot  = blk >> 4;

    int tid  = threadIdx.x;
    int tx   = tid & 15;
    int ty   = tid >> 4;          // 0..7
    int w    = tid >> 5;          // warp 0..3
    int lane = tid & 31;
    int hw   = (lane >> 4) << 4;  // 0 or 16: half-warp row offset inside A tile
    int h0   = chunk * 16;

    const float* Ud  = U    + dir * (KK2 * G5);
    const float* Wxd = Wx   + dir * G5;
    const float* bd  = bias + dir * G5;

    // ---- one-time: persistent U slice into smem (R9-identical values/order) ----
    for (int i = tid; i < US_SZ; i += 128) {
        int kk   = i / 80;
        int col  = i - kk * 80;
        int gate = col >> 4;
        int hh   = col & 15;
        smf[i] = Ud[kk * G5 + gate * 64 + h0 + hh];
    }

    int hcol = h0 + tx;
    float wxb[5], bb[5];
    #pragma unroll
    for (int g = 0; g < 5; ++g) {
        wxb[g] = Wxd[g * 64 + hcol];
        bb[g]  = bd [g * 64 + hcol];
    }
    __syncthreads();

    float* Aw = &smf[AW_OFF + w * AW_WARP];

    unsigned gen = 0u;

    for (int d = 0; d < 2 * GS - 1; ++d) {
        int rlo = d - (GS - 1); if (rlo < 0) rlo = 0;
        int k = d + 1;
        if (2 * GS - 1 - d < k) k = 2 * GS - 1 - d;
        if (k > GS) k = GS;

        if (slot < k) {
            int r = rlo + slot;
            int c = d - r;

            const float* hL = (c > 0) ? &g_h[dir][r][c-1][0][0] : nullptr;
            const float* hU = (r > 0) ? &g_h[dir][r-1][c][0][0] : nullptr;

            int rr = (dir & 2) ? (GS - 1 - r) : r;
            int cc = (dir & 1) ? (GS - 1 - c) : c;
            smf[XS_OFF + tid] = x[tid * (GS * GS) + rr * GS + cc];
            __syncwarp();   // xs consumed only within the writing warp

            u64 acc[8][5];
            #pragma unroll
            for (int p = 0; p < 8; ++p)
                #pragma unroll
                for (int g = 0; g < 5; ++g) acc[p][g] = 0ull;

            // ---- one K half: warp-private staged A, dbl-buffered, syncwarp only
            #define K_HALF(src, uofs)                                              \
            {                                                                       \
                const float* srow = (src) + (32 * w + lane) * NH;                   \
                const float* Uh   = &smf[(uofs) * 80];                              \
                float4 v0 = *(const float4*)(srow);                                 \
                float4 v1 = *(const float4*)(srow + 4);                             \
                Aw[0*36+lane]=v0.x; Aw[1*36+lane]=v0.y; Aw[2*36+lane]=v0.z;         \
                Aw[3*36+lane]=v0.w; Aw[4*36+lane]=v1.x; Aw[5*36+lane]=v1.y;         \
                Aw[6*36+lane]=v1.z; Aw[7*36+lane]=v1.w;                             \
                __syncwarp();                                                       \
                _Pragma("unroll")                                                   \
                for (int t = 0; t < 8; ++t) {                                       \
                    if (t < 7) {                                                    \
                        v0 = *(const float4*)(srow + (t + 1) * 8);                  \
                        v1 = *(const float4*)(srow + (t + 1) * 8 + 4);              \
                    }                                                               \
                    const float* Ab = Aw + (t & 1) * 288 + hw;                      \
                    const float* Ut = Uh + t * 8 * 80;                              \
                    _Pragma("unroll")                                               \
                    for (int kk = 0; kk < 8; ++kk) {                                \
                        ulonglong2 A0 = *(const ulonglong2*)(Ab + kk * 36);         \
                        ulonglong2 A1 = *(const ulonglong2*)(Ab + kk * 36 + 4);     \
                        ulonglong2 A2 = *(const ulonglong2*)(Ab + kk * 36 + 8);     \
                        ulonglong2 A3 = *(const ulonglong2*)(Ab + kk * 36 + 12);    \
                        u64 a[8] = {A0.x, A0.y, A1.x, A1.y, A2.x, A2.y, A3.x, A3.y};\
                        u64 bf[5];                                                  \
                        _Pragma("unroll")                                           \
                        for (int g = 0; g < 5; ++g)                                 \
                            bf[g] = dup2(Ut[kk * 80 + g * 16 + tx]);                \
                        _Pragma("unroll")                                           \
                        for (int p = 0; p < 8; ++p)                                 \
                            _Pragma("unroll")                                       \
                            for (int g = 0; g < 5; ++g)                             \
                                fma2(acc[p][g], a[p], bf[g]);                       \
                    }                                                               \
                    if (t < 7) {                                                    \
                        float* Abn = Aw + ((t + 1) & 1) * 288;                      \
                        Abn[0*36+lane]=v0.x; Abn[1*36+lane]=v0.y;                   \
                        Abn[2*36+lane]=v0.z; Abn[3*36+lane]=v0.w;                   \
                        Abn[4*36+lane]=v1.x; Abn[5*36+lane]=v1.y;                   \
                        Abn[6*36+lane]=v1.z; Abn[7*36+lane]=v1.w;                   \
                    }                                                               \
                    __syncwarp();                                                   \
                }                                                                   \
            }

            if (hL) K_HALF(hL, 0)      // k = 0..63   (same order as R9)
            if (hU) K_HALF(hU, 64)     // k = 64..127
            #undef K_HALF

            // Fused gate epilogue (R9 verbatim: c_left and c_up from global)
            const float* cLp = (c > 0) ? &g_c[dir][r][c-1][0][0] : nullptr;
            const float* cUp = (r > 0) ? &g_c[dir][r-1][c][0][0] : nullptr;
            float* hOut = &g_h[dir][r][c][0][0];
            float* cOut = &g_c[dir][r][c][0][0];

            #pragma unroll
            for (int p = 0; p < 8; ++p) {
                int row0 = ty * 16 + 2 * p;
                float zl[5], zh[5];
                #pragma unroll
                for (int g = 0; g < 5; ++g) unpack2(acc[p][g], zl[g], zh[g]);
                #pragma unroll
                for (int half = 0; half < 2; ++half) {
                    int row = row0 + half;
                    float xv = smf[XS_OFF + row];
                    float z0 = (half ? zh[0] : zl[0]) + xv * wxb[0] + bb[0]; // i
                    float z1 = (half ? zh[1] : zl[1]) + xv * wxb[1] + bb[1]; // f_left
                    float z2 = (half ? zh[2] : zl[2]) + xv * wxb[2] + bb[2]; // f_up
                    float z3 = (half ? zh[3] : zl[3]) + xv * wxb[3] + bb[3]; // o
                    float z4 = (half ? zh[4] : zl[4]) + xv * wxb[4] + bb[4]; // g
                    float cl = cLp ? cLp[row * NH + hcol] : 0.0f;
                    float cu = cUp ? cUp[row * NH + hcol] : 0.0f;
                    float cn = sigf(z0) * tanh_acc(z4) + sigf(z1) * cl + sigf(z2) * cu;
                    float hn = sigf(z3) * tanh_acc(cn);
                    cOut[row * NH + hcol] = cn;
                    hOut[row * NH + hcol] = hn;
                }
            }
        }

        dir_barrier(dir, tid, gen);
        gen++;
    }
}

// z1 = relu(hfinal @ W1 + b1); hfinal[b][dir*64+h] = g_h[dir][27][27][b][h]
__global__ void head1_kernel(const float* __restrict__ W1,
                             const float* __restrict__ b1)
{
    __shared__ float a[ND * NH];
    int b = blockIdx.y;
    int n = blockIdx.x * 256 + threadIdx.x;
    {
        int dcol = threadIdx.x;
        int dir = dcol >> 6, hh = dcol & 63;
        a[dcol] = g_h[dir][GS - 1][GS - 1][b][hh];
    }
    __syncthreads();
    float acc = b1[n];
    #pragma unroll 8
    for (int k = 0; k < ND * NH; ++k)
        acc = fmaf(a[k], W1[k * FCH + n], acc);
    g_z1[b][n] = fmaxf(acc, 0.0f);
}

// out = softmax(z1 @ W2 + b2)
__global__ void head2_kernel(const float* __restrict__ W2,
                             const float* __restrict__ b2,
                             float* __restrict__ out)
{
    __shared__ float logit[NOUT];
    int b    = blockIdx.x;
    int tid  = threadIdx.x;        // 320 threads = 10 warps
    int w    = tid >> 5;
    int lane = tid & 31;
    float acc = 0.0f;
    for (int k = lane; k < FCH; k += 32)
        acc = fmaf(g_z1[b][k], W2[k * NOUT + w], acc);
    #pragma unroll
    for (int o = 16; o; o >>= 1)
        acc += __shfl_down_sync(0xffffffffu, acc, o);
    if (lane == 0) logit[w] = acc + b2[w];
    __syncthreads();
    if (tid == 0) {
        float m = -1e30f;
        #pragma unroll
        for (int j = 0; j < NOUT; ++j) m = fmaxf(m, logit[j]);
        float e[NOUT], s = 0.0f;
        #pragma unroll
        for (int j = 0; j < NOUT; ++j) { e[j] = __expf(logit[j] - m); s += e[j]; }
        float inv = 1.0f / s;
        #pragma unroll
        for (int j = 0; j < NOUT; ++j) out[b * NOUT + j] = e[j] * inv;
    }
}

extern "C" void kernel_launch(void* const* d_in, const int* in_sizes, int n_in,
                              void* d_out, int out_size)
{
    const float* x  = (const float*)d_in[0];
    const float* Wx = (const float*)d_in[1];
    const float* U  = (const float*)d_in[2];
    const float* bb = (const float*)d_in[3];
    const float* W1 = (const float*)d_in[4];
    const float* b1 = (const float*)d_in[5];
    const float* W2 = (const float*)d_in[6];
    const float* b2 = (const float*)d_in[7];
    float* out = (float*)d_out;

    cudaFuncSetAttribute(mdlstm_wave,
                         cudaFuncAttributeMaxDynamicSharedMemorySize, SMEM_BYTES);

    init_kernel<<<1, 32>>>();
    mdlstm_wave<<<NBLK, 128, SMEM_BYTES>>>(x, Wx, U, bb);
    head1_kernel<<<dim3(2, NB), 256>>>(W1, b1);
    head2_kernel<<<NB, 320>>>(W2, b2, out);
}

// round 13
// speedup vs baseline: 1.2973x; 1.0367x over previous
#include <cuda_runtime.h>
#include <math.h>

#define GS   28
#define NB   128
#define NH   64
#define ND   4
#define G5   320
#define KK2  128
#define FCH  512
#define NOUT 10
#define NBLK      448     // 28 slots * 4 dirs * 4 chunk16
#define BLK_PER_DIR 112u

// dynamic smem (floats):
//   Us[128][80]   : 10240 floats (persistent U slice for this (dir,chunk))
//   As[2][8][130] :  2080 floats (A k-tiles of 8, transposed, padded, dbl-buf)
//   xs[128]       :   128 floats
#define US_SZ    10240
#define AS_OFF   10240
#define AS_TILE  1040          // 8*130
#define XS_OFF   (10240 + 2080)
#define SMEM_FLOATS (XS_OFF + 128)
#define SMEM_BYTES  (SMEM_FLOATS * 4)   // 49792

// Recurrent state: [dir][row][col][batch][h]
__device__ float g_h[ND][GS][GS][NB][NH];
__device__ float g_c[ND][GS][GS][NB][NH];
__device__ float g_z1[NB][FCH];

struct __align__(128) Bar { unsigned gen; unsigned cnt; };
__device__ Bar g_bar[ND];

typedef unsigned long long u64;

__device__ __forceinline__ void fma2(u64 &d, u64 a, u64 b) {
    asm("fma.rn.f32x2 %0, %1, %2, %0;" : "+l"(d) : "l"(a), "l"(b));
}
__device__ __forceinline__ u64 dup2(float v) {
    u64 r; asm("mov.b64 %0, {%1, %1};" : "=l"(r) : "f"(v)); return r;
}
__device__ __forceinline__ void unpack2(u64 v, float &lo, float &hi) {
    asm("mov.b64 {%0, %1}, %2;" : "=f"(lo), "=f"(hi) : "l"(v));
}
__device__ __forceinline__ float sigf(float x) { return 1.0f / (1.0f + __expf(-x)); }
__device__ __forceinline__ float tanh_acc(float x) {
    float e = __expf(-2.0f * fabsf(x));
    float t = (1.0f - e) / (1.0f + e);
    return copysignf(t, x);
}

__global__ void init_kernel() {
    if (threadIdx.x < ND) { g_bar[threadIdx.x].gen = 0u; g_bar[threadIdx.x].cnt = 0u; }
}

// Dummy kernel purely to shift which launch ncu's -s window captures.
__global__ void align_kernel() {}

// Per-dir sense-reversing barrier (112 blocks per dir), nanosleep backoff.
// (Proven construct from R4/R9 -- unchanged.)
__device__ __forceinline__ void dir_barrier(int dir, int tid, unsigned gen) {
    __threadfence();
    __syncthreads();
    if (tid == 0) {
        if (atomicAdd(&g_bar[dir].cnt, 1u) == BLK_PER_DIR - 1u) {
            g_bar[dir].cnt = 0u;
            asm volatile("st.release.gpu.global.b32 [%0], %1;"
                         :: "l"(&g_bar[dir].gen), "r"(gen + 1u) : "memory");
        } else {
            unsigned v;
            do {
                __nanosleep(64);
                asm volatile("ld.acquire.gpu.global.b32 %0, [%1];"
                             : "=r"(v) : "l"(&g_bar[dir].gen) : "memory");
            } while (v == gen);
        }
    }
    __syncthreads();
    __threadfence();
}

// Persistent wavefront: R9 structure (persistent-U smem, k8 dbl-buf A),
// plus null-half GEMM skip (adds exact zeros -> bit-identical result).
// blk decode identical to R4/R9: chunk = blk&3, dir = (blk>>2)&3, slot = blk>>4.
__global__ __launch_bounds__(128, 4) void mdlstm_wave(
    const float* __restrict__ x,
    const float* __restrict__ Wx,
    const float* __restrict__ U,
    const float* __restrict__ bias)
{
    extern __shared__ __align__(16) float smf[];

    int blk   = blockIdx.x;
    int chunk = blk & 3;
    int dir   = (blk >> 2) & 3;
    int slot  = blk >> 4;

    int tid = threadIdx.x;
    int tx  = tid & 15;
    int ty  = tid >> 4;           // 0..7
    int h0  = chunk * 16;

    const float* Ud  = U    + dir * (KK2 * G5);
    const float* Wxd = Wx   + dir * G5;
    const float* bd  = bias + dir * G5;

    // ---- one-time: persistent U slice into smem ----
    // Us[kglob][col], col = gate*16 + hh  (same values/order as R9)
    for (int i = tid; i < US_SZ; i += 128) {
        int kk   = i / 80;
        int col  = i - kk * 80;
        int gate = col >> 4;
        int hh   = col & 15;
        smf[i] = Ud[kk * G5 + gate * 64 + h0 + hh];
    }

    int hcol = h0 + tx;
    float wxb[5], bb[5];
    #pragma unroll
    for (int g = 0; g < 5; ++g) {
        wxb[g] = Wxd[g * 64 + hcol];
        bb[g]  = bd [g * 64 + hcol];
    }
    __syncthreads();

    unsigned gen = 0u;

    for (int d = 0; d < 2 * GS - 1; ++d) {
        int rlo = d - (GS - 1); if (rlo < 0) rlo = 0;
        int k = d + 1;
        if (2 * GS - 1 - d < k) k = 2 * GS - 1 - d;
        if (k > GS) k = GS;

        if (slot < k) {
            int r = rlo + slot;
            int c = d - r;

            const float* hL = (c > 0) ? &g_h[dir][r][c-1][0][0] : nullptr;
            const float* hU = (r > 0) ? &g_h[dir][r-1][c][0][0] : nullptr;

            int rr = (dir & 2) ? (GS - 1 - r) : r;
            int cc = (dir & 1) ? (GS - 1 - c) : c;
            smf[XS_OFF + tid] = x[tid * (GS * GS) + rr * GS + cc];
            __syncthreads();

            u64 acc[8][5];
            #pragma unroll
            for (int p = 0; p < 8; ++p)
                #pragma unroll
                for (int g = 0; g < 5; ++g) acc[p][g] = 0ull;

            // A k-tile fill: within a half, tile t_ covers kofs = t_*8..t_*8+7
            // of that half's 64 k values. src is non-null here (half skipped
            // entirely when null -- equals adding exact zeros).
            #define FILL_A(buf, srcp, t_)                                      \
            {                                                                   \
                int kofs = (t_) * 8;                                            \
                float* Ab = &smf[AS_OFF + (buf) * AS_TILE];                     \
                _Pragma("unroll")                                               \
                for (int j = 0; j < 8; ++j) {                                   \
                    int i  = tid + j * 128;                                     \
                    int b  = i >> 3;                                            \
                    int kk = i & 7;                                             \
                    Ab[kk * 130 + b] = (srcp)[b * NH + kofs + kk];              \
                }                                                               \
            }

            // Halves in R9 k-order: hL covers kglob 0..63, hU covers 64..127.
            #pragma unroll
            for (int half = 0; half < 2; ++half) {
                const float* src = half ? hU : hL;
                if (!src) continue;                    // uniform across block
                const float* Uh = &smf[half * 64 * 80];

                FILL_A(0, src, 0)
                __syncthreads();

                #pragma unroll 4
                for (int t = 0; t < 8; ++t) {
                    if (t < 7) FILL_A((t + 1) & 1, src, t + 1)

                    const float* Ab = &smf[AS_OFF + (t & 1) * AS_TILE];
                    const float* Ut = Uh + t * 8 * 80;
                    #pragma unroll
                    for (int kk = 0; kk < 8; ++kk) {
                        u64 a[8], bf[5];
                        #pragma unroll
                        for (int p = 0; p < 8; ++p)
                            a[p] = *(const u64*)&Ab[kk * 130 + ty * 16 + 2 * p];
                        #pragma unroll
                        for (int g = 0; g < 5; ++g)
                            bf[g] = dup2(Ut[kk * 80 + g * 16 + tx]);
                        #pragma unroll
                        for (int p = 0; p < 8; ++p)
                            #pragma unroll
                            for (int g = 0; g < 5; ++g)
                                fma2(acc[p][g], a[p], bf[g]);
                    }
                    __syncthreads();
                }
            }
            #undef FILL_A

            // Fused gate epilogue (R9 verbatim: c_left and c_up from global)
            const float* cLp = (c > 0) ? &g_c[dir][r][c-1][0][0] : nullptr;
            const float* cUp = (r > 0) ? &g_c[dir][r-1][c][0][0] : nullptr;
            float* hOut = &g_h[dir][r][c][0][0];
            float* cOut = &g_c[dir][r][c][0][0];

            #pragma unroll
            for (int p = 0; p < 8; ++p) {
                int row0 = ty * 16 + 2 * p;
                float zl[5], zh[5];
                #pragma unroll
                for (int g = 0; g < 5; ++g) unpack2(acc[p][g], zl[g], zh[g]);
                #pragma unroll
                for (int half = 0; half < 2; ++half) {
                    int row = row0 + half;
                    float xv = smf[XS_OFF + row];
                    float z0 = (half ? zh[0] : zl[0]) + xv * wxb[0] + bb[0]; // i
                    float z1 = (half ? zh[1] : zl[1]) + xv * wxb[1] + bb[1]; // f_left
                    float z2 = (half ? zh[2] : zl[2]) + xv * wxb[2] + bb[2]; // f_up
                    float z3 = (half ? zh[3] : zl[3]) + xv * wxb[3] + bb[3]; // o
                    float z4 = (half ? zh[4] : zl[4]) + xv * wxb[4] + bb[4]; // g
                    float cl = cLp ? cLp[row * NH + hcol] : 0.0f;
                    float cu = cUp ? cUp[row * NH + hcol] : 0.0f;
                    float cn = sigf(z0) * tanh_acc(z4) + sigf(z1) * cl + sigf(z2) * cu;
                    float hn = sigf(z3) * tanh_acc(cn);
                    cOut[row * NH + hcol] = cn;
                    hOut[row * NH + hcol] = hn;
                }
            }
        }

        dir_barrier(dir, tid, gen);
        gen++;
    }
}

// z1 = relu(hfinal @ W1 + b1); hfinal[b][dir*64+h] = g_h[dir][27][27][b][h]
__global__ void head1_kernel(const float* __restrict__ W1,
                             const float* __restrict__ b1)
{
    __shared__ float a[ND * NH];
    int b = blockIdx.y;
    int n = blockIdx.x * 256 + threadIdx.x;
    {
        int dcol = threadIdx.x;
        int dir = dcol >> 6, hh = dcol & 63;
        a[dcol] = g_h[dir][GS - 1][GS - 1][b][hh];
    }
    __syncthreads();
    float acc = b1[n];
    #pragma unroll 8
    for (int k = 0; k < ND * NH; ++k)
        acc = fmaf(a[k], W1[k * FCH + n], acc);
    g_z1[b][n] = fmaxf(acc, 0.0f);
}

// out = softmax(z1 @ W2 + b2)
__global__ void head2_kernel(const float* __restrict__ W2,
                             const float* __restrict__ b2,
                             float* __restrict__ out)
{
    __shared__ float logit[NOUT];
    int b    = blockIdx.x;
    int tid  = threadIdx.x;        // 320 threads = 10 warps
    int w    = tid >> 5;
    int lane = tid & 31;
    float acc = 0.0f;
    for (int k = lane; k < FCH; k += 32)
        acc = fmaf(g_z1[b][k], W2[k * NOUT + w], acc);
    #pragma unroll
    for (int o = 16; o; o >>= 1)
        acc += __shfl_down_sync(0xffffffffu, acc, o);
    if (lane == 0) logit[w] = acc + b2[w];
    __syncthreads();
    if (tid == 0) {
        float m = -1e30f;
        #pragma unroll
        for (int j = 0; j < NOUT; ++j) m = fmaxf(m, logit[j]);
        float e[NOUT], s = 0.0f;
        #pragma unroll
        for (int j = 0; j < NOUT; ++j) { e[j] = __expf(logit[j] - m); s += e[j]; }
        float inv = 1.0f / s;
        #pragma unroll
        for (int j = 0; j < NOUT; ++j) out[b * NOUT + j] = e[j] * inv;
    }
}

extern "C" void kernel_launch(void* const* d_in, const int* in_sizes, int n_in,
                              void* d_out, int out_size)
{
    const float* x  = (const float*)d_in[0];
    const float* Wx = (const float*)d_in[1];
    const float* U  = (const float*)d_in[2];
    const float* bb = (const float*)d_in[3];
    const float* W1 = (const float*)d_in[4];
    const float* b1 = (const float*)d_in[5];
    const float* W2 = (const float*)d_in[6];
    const float* b2 = (const float*)d_in[7];
    float* out = (float*)d_out;

    cudaFuncSetAttribute(mdlstm_wave,
                         cudaFuncAttributeMaxDynamicSharedMemorySize, SMEM_BYTES);

    init_kernel<<<1, 32>>>();
    align_kernel<<<1, 32>>>();   // shifts ncu's -s window onto mdlstm_wave
    mdlstm_wave<<<NBLK, 128, SMEM_BYTES>>>(x, Wx, U, bb);
    head1_kernel<<<dim3(2, NB), 256>>>(W1, b1);
    head2_kernel<<<NB, 320>>>(W2, b2, out);
}

// round 14
// speedup vs baseline: 1.3600x; 1.0484x over previous
#include <cuda_runtime.h>
#include <math.h>

#define GS   28
#define NB   128
#define NH   64
#define ND   4
#define G5   320
#define KK2  128
#define FCH  512
#define NOUT 10
#define NBLK      448     // 28 slots * 4 dirs * 4 chunk16
#define BLK_PER_DIR 112u

// dynamic smem (floats):
//   Us[128][80]   : 10240 floats (persistent U slice for this (dir,chunk))
//   As[2][8][132] :  2112 floats (A k-tiles of 8, transposed, pad 132 for LDS.128)
//   xs[128]       :   128 floats
#define US_SZ    10240
#define AS_OFF   10240
#define AS_TILE  1056          // 8*132
#define XS_OFF   (AS_OFF + 2 * AS_TILE)   // 12352
#define SMEM_FLOATS (XS_OFF + 128)
#define SMEM_BYTES  (SMEM_FLOATS * 4)     // 49920

// Recurrent state: [dir][row][col][batch][h]
__device__ float g_h[ND][GS][GS][NB][NH];
__device__ float g_c[ND][GS][GS][NB][NH];
__device__ float g_z1[NB][FCH];

struct __align__(128) Bar { unsigned gen; unsigned cnt; };
__device__ Bar g_bar[ND];

typedef unsigned long long u64;

__device__ __forceinline__ void fma2(u64 &d, u64 a, u64 b) {
    asm("fma.rn.f32x2 %0, %1, %2, %0;" : "+l"(d) : "l"(a), "l"(b));
}
__device__ __forceinline__ u64 dup2(float v) {
    u64 r; asm("mov.b64 %0, {%1, %1};" : "=l"(r) : "f"(v)); return r;
}
__device__ __forceinline__ void unpack2(u64 v, float &lo, float &hi) {
    asm("mov.b64 {%0, %1}, %2;" : "=f"(lo), "=f"(hi) : "l"(v));
}
__device__ __forceinline__ float sigf(float x) { return 1.0f / (1.0f + __expf(-x)); }
__device__ __forceinline__ float tanh_acc(float x) {
    float e = __expf(-2.0f * fabsf(x));
    float t = (1.0f - e) / (1.0f + e);
    return copysignf(t, x);
}

__global__ void init_kernel() {
    if (threadIdx.x < ND) { g_bar[threadIdx.x].gen = 0u; g_bar[threadIdx.x].cnt = 0u; }
}

// Dummy kernel: ncu captures per-iteration launch position 4, so two of
// these before mdlstm_wave put the wave kernel in the capture window.
__global__ void align_kernel() {}

// Per-dir sense-reversing barrier (112 blocks per dir), nanosleep backoff.
// (Proven construct from R4/R9 -- unchanged.)
__device__ __forceinline__ void dir_barrier(int dir, int tid, unsigned gen) {
    __threadfence();
    __syncthreads();
    if (tid == 0) {
        if (atomicAdd(&g_bar[dir].cnt, 1u) == BLK_PER_DIR - 1u) {
            g_bar[dir].cnt = 0u;
            asm volatile("st.release.gpu.global.b32 [%0], %1;"
                         :: "l"(&g_bar[dir].gen), "r"(gen + 1u) : "memory");
        } else {
            unsigned v;
            do {
                __nanosleep(64);
                asm volatile("ld.acquire.gpu.global.b32 %0, [%1];"
                             : "=r"(v) : "l"(&g_bar[dir].gen) : "memory");
            } while (v == gen);
        }
    }
    __syncthreads();
    __threadfence();
}

// Persistent wavefront: R9 structure (persistent-U smem, k8 dbl-buf A,
// fused 16-tile pipeline, zero-fill null halves) with LDS.128 A consume.
// blk decode identical to R4/R9: chunk = blk&3, dir = (blk>>2)&3, slot = blk>>4.
__global__ __launch_bounds__(128, 4) void mdlstm_wave(
    const float* __restrict__ x,
    const float* __restrict__ Wx,
    const float* __restrict__ U,
    const float* __restrict__ bias)
{
    extern __shared__ __align__(16) float smf[];

    int blk   = blockIdx.x;
    int chunk = blk & 3;
    int dir   = (blk >> 2) & 3;
    int slot  = blk >> 4;

    int tid = threadIdx.x;
    int tx  = tid & 15;
    int ty  = tid >> 4;           // 0..7
    int h0  = chunk * 16;

    const float* Ud  = U    + dir * (KK2 * G5);
    const float* Wxd = Wx   + dir * G5;
    const float* bd  = bias + dir * G5;

    // ---- one-time: persistent U slice into smem (R9-identical values/order) ----
    for (int i = tid; i < US_SZ; i += 128) {
        int kk   = i / 80;
        int col  = i - kk * 80;
        int gate = col >> 4;
        int hh   = col & 15;
        smf[i] = Ud[kk * G5 + gate * 64 + h0 + hh];
    }

    int hcol = h0 + tx;
    float wxb[5], bb[5];
    #pragma unroll
    for (int g = 0; g < 5; ++g) {
        wxb[g] = Wxd[g * 64 + hcol];
        bb[g]  = bd [g * 64 + hcol];
    }
    __syncthreads();

    unsigned gen = 0u;

    for (int d = 0; d < 2 * GS - 1; ++d) {
        int rlo = d - (GS - 1); if (rlo < 0) rlo = 0;
        int k = d + 1;
        if (2 * GS - 1 - d < k) k = 2 * GS - 1 - d;
        if (k > GS) k = GS;

        if (slot < k) {
            int r = rlo + slot;
            int c = d - r;

            const float* hL = (c > 0) ? &g_h[dir][r][c-1][0][0] : nullptr;
            const float* hU = (r > 0) ? &g_h[dir][r-1][c][0][0] : nullptr;

            int rr = (dir & 2) ? (GS - 1 - r) : r;
            int cc = (dir & 1) ? (GS - 1 - c) : c;
            smf[XS_OFF + tid] = x[tid * (GS * GS) + rr * GS + cc];
            __syncthreads();

            u64 acc[8][5];
            #pragma unroll
            for (int p = 0; p < 8; ++p)
                #pragma unroll
                for (int g = 0; g < 5; ++g) acc[p][g] = 0ull;

            // A k-tile fill: tile t covers kglob = t*8 .. t*8+7
            // (t < 8 -> hL half, t >= 8 -> hU half; same k order as R9;
            //  null half zero-filled, identical to R9)
            #define FILL_A(buf, t_)                                            \
            {                                                                   \
                const float* src = ((t_) < 8) ? hL : hU;                        \
                int kofs = ((t_) & 7) * 8;                                      \
                float* Ab = &smf[AS_OFF + (buf) * AS_TILE];                     \
                _Pragma("unroll")                                               \
                for (int j = 0; j < 8; ++j) {                                   \
                    int i  = tid + j * 128;                                     \
                    int b  = i >> 3;                                            \
                    int kk = i & 7;                                             \
                    Ab[kk * 132 + b] = src ? src[b * NH + kofs + kk] : 0.0f;    \
                }                                                               \
            }

            FILL_A(0, 0)
            __syncthreads();

            #pragma unroll 4
            for (int t = 0; t < 16; ++t) {
                if (t < 15) FILL_A((t + 1) & 1, t + 1)

                const float* Ab = &smf[AS_OFF + (t & 1) * AS_TILE];
                const float* Ut = &smf[t * 8 * 80];
                #pragma unroll
                for (int kk = 0; kk < 8; ++kk) {
                    // 4x LDS.128; value order matches R9's a[p] exactly
                    const float* ap = &Ab[kk * 132 + ty * 16];
                    ulonglong2 A0 = *(const ulonglong2*)(ap);
                    ulonglong2 A1 = *(const ulonglong2*)(ap + 4);
                    ulonglong2 A2 = *(const ulonglong2*)(ap + 8);
                    ulonglong2 A3 = *(const ulonglong2*)(ap + 12);
                    u64 a[8] = {A0.x, A0.y, A1.x, A1.y, A2.x, A2.y, A3.x, A3.y};
                    u64 bf[5];
                    #pragma unroll
                    for (int g = 0; g < 5; ++g)
                        bf[g] = dup2(Ut[kk * 80 + g * 16 + tx]);
                    #pragma unroll
                    for (int p = 0; p < 8; ++p)
                        #pragma unroll
                        for (int g = 0; g < 5; ++g)
                            fma2(acc[p][g], a[p], bf[g]);
                }
                __syncthreads();
            }
            #undef FILL_A

            // Fused gate epilogue (R9 verbatim: c_left and c_up from global)
            const float* cLp = (c > 0) ? &g_c[dir][r][c-1][0][0] : nullptr;
            const float* cUp = (r > 0) ? &g_c[dir][r-1][c][0][0] : nullptr;
            float* hOut = &g_h[dir][r][c][0][0];
            float* cOut = &g_c[dir][r][c][0][0];

            #pragma unroll
            for (int p = 0; p < 8; ++p) {
                int row0 = ty * 16 + 2 * p;
                float zl[5], zh[5];
                #pragma unroll
                for (int g = 0; g < 5; ++g) unpack2(acc[p][g], zl[g], zh[g]);
                #pragma unroll
                for (int half = 0; half < 2; ++half) {
                    int row = row0 + half;
                    float xv = smf[XS_OFF + row];
                    float z0 = (half ? zh[0] : zl[0]) + xv * wxb[0] + bb[0]; // i
                    float z1 = (half ? zh[1] : zl[1]) + xv * wxb[1] + bb[1]; // f_left
                    float z2 = (half ? zh[2] : zl[2]) + xv * wxb[2] + bb[2]; // f_up
                    float z3 = (half ? zh[3] : zl[3]) + xv * wxb[3] + bb[3]; // o
                    float z4 = (half ? zh[4] : zl[4]) + xv * wxb[4] + bb[4]; // g
                    float cl = cLp ? cLp[row * NH + hcol] : 0.0f;
                    float cu = cUp ? cUp[row * NH + hcol] : 0.0f;
                    float cn = sigf(z0) * tanh_acc(z4) + sigf(z1) * cl + sigf(z2) * cu;
                    float hn = sigf(z3) * tanh_acc(cn);
                    cOut[row * NH + hcol] = cn;
                    hOut[row * NH + hcol] = hn;
                }
            }
        }

        dir_barrier(dir, tid, gen);
        gen++;
    }
}

// z1 = relu(hfinal @ W1 + b1); hfinal[b][dir*64+h] = g_h[dir][27][27][b][h]
__global__ void head1_kernel(const float* __restrict__ W1,
                             const float* __restrict__ b1)
{
    __shared__ float a[ND * NH];
    int b = blockIdx.y;
    int n = blockIdx.x * 256 + threadIdx.x;
    {
        int dcol = threadIdx.x;
        int dir = dcol >> 6, hh = dcol & 63;
        a[dcol] = g_h[dir][GS - 1][GS - 1][b][hh];
    }
    __syncthreads();
    float acc = b1[n];
    #pragma unroll 8
    for (int k = 0; k < ND * NH; ++k)
        acc = fmaf(a[k], W1[k * FCH + n], acc);
    g_z1[b][n] = fmaxf(acc, 0.0f);
}

// out = softmax(z1 @ W2 + b2)
__global__ void head2_kernel(const float* __restrict__ W2,
                             const float* __restrict__ b2,
                             float* __restrict__ out)
{
    __shared__ float logit[NOUT];
    int b    = blockIdx.x;
    int tid  = threadIdx.x;        // 320 threads = 10 warps
    int w    = tid >> 5;
    int lane = tid & 31;
    float acc = 0.0f;
    for (int k = lane; k < FCH; k += 32)
        acc = fmaf(g_z1[b][k], W2[k * NOUT + w], acc);
    #pragma unroll
    for (int o = 16; o; o >>= 1)
        acc += __shfl_down_sync(0xffffffffu, acc, o);
    if (lane == 0) logit[w] = acc + b2[w];
    __syncthreads();
    if (tid == 0) {
        float m = -1e30f;
        #pragma unroll
        for (int j = 0; j < NOUT; ++j) m = fmaxf(m, logit[j]);
        float e[NOUT], s = 0.0f;
        #pragma unroll
        for (int j = 0; j < NOUT; ++j) { e[j] = __expf(logit[j] - m); s += e[j]; }
        float inv = 1.0f / s;
        #pragma unroll
        for (int j = 0; j < NOUT; ++j) out[b * NOUT + j] = e[j] * inv;
    }
}

extern "C" void kernel_launch(void* const* d_in, const int* in_sizes, int n_in,
                              void* d_out, int out_size)
{
    const float* x  = (const float*)d_in[0];
    const float* Wx = (const float*)d_in[1];
    const float* U  = (const float*)d_in[2];
    const float* bb = (const float*)d_in[3];
    const float* W1 = (const float*)d_in[4];
    const float* b1 = (const float*)d_in[5];
    const float* W2 = (const float*)d_in[6];
    const float* b2 = (const float*)d_in[7];
    float* out = (float*)d_out;

    cudaFuncSetAttribute(mdlstm_wave,
                         cudaFuncAttributeMaxDynamicSharedMemorySize, SMEM_BYTES);

    init_kernel<<<1, 32>>>();
    align_kernel<<<1, 32>>>();   // capture-window padding (position 2)
    align_kernel<<<1, 32>>>();   // capture-window padding (position 3)
    mdlstm_wave<<<NBLK, 128, SMEM_BYTES>>>(x, Wx, U, bb);  // position 4 -> profiled
    head1_kernel<<<dim3(2, NB), 256>>>(W1, b1);
    head2_kernel<<<NB, 320>>>(W2, b2, out);
}